// round 4
// baseline (speedup 1.0000x reference)
#include <cuda_runtime.h>
#include <math.h>

// Problem constants
#define BATCH 2
#define SEQ   2048
#define HID   2048
#define NH    16
#define HD    128
#define MTOT  (BATCH*SEQ)   // 4096

// ---------------- scratch (device globals: allocation-free rule) ----------------
__device__ float g_q[BATCH*SEQ*HID];
__device__ float g_k[BATCH*SEQ*HID];
__device__ float g_v[BATCH*SEQ*HID];
__device__ float g_ctx[BATCH*SEQ*HID];
__device__ float g_sin[SEQ*HD];
__device__ float g_cos[SEQ*HD];

// ---------------- RoPE sin/cos table (double precision, tiny kernel) ------------
__global__ void sincos_table_kernel() {
    int idx = blockIdx.x * blockDim.x + threadIdx.x;   // over SEQ * HD/2
    if (idx >= SEQ * (HD / 2)) return;
    int pos = idx / (HD / 2);
    int j   = idx % (HD / 2);
    double inv = exp((-2.0 * (double)j / (double)HD) * log(10000.0));
    double ang = (double)pos * inv;
    float s = (float)sin(ang);
    float c = (float)cos(ang);
    g_sin[pos * HD + 2 * j]     = s;
    g_sin[pos * HD + 2 * j + 1] = s;
    g_cos[pos * HD + 2 * j]     = c;
    g_cos[pos * HD + 2 * j + 1] = c;
}

// ---------------- RoPE apply (q and k in-place) --------------------------------
__global__ void rope_kernel() {
    int idx = blockIdx.x * blockDim.x + threadIdx.x;   // over BATCH*SEQ*HID/2 pairs
    const int total = BATCH * SEQ * HID / 2;
    if (idx >= total) return;
    int pair = idx % (HID / 2);        // pair index within row
    int row  = idx / (HID / 2);
    int s    = row % SEQ;
    int d    = (pair * 2) % HD;        // even position within head
    float sn = g_sin[s * HD + d];
    float cs = g_cos[s * HD + d];
    int base = row * HID + pair * 2;
    float2 q = *(float2*)&g_q[base];
    float2 k = *(float2*)&g_k[base];
    float2 qo, ko;
    qo.x = q.x * cs - q.y * sn;  qo.y = q.y * cs + q.x * sn;
    ko.x = k.x * cs - k.y * sn;  ko.y = k.y * cs + k.x * sn;
    *(float2*)&g_q[base] = qo;
    *(float2*)&g_k[base] = ko;
}

// ---------------- SGEMM with bias: C[M,N] = A[M,K] * W[K,N] + bias -------------
// Double-buffered SMEM pipeline: prefetch next K-slab into registers during
// compute, ping-pong SMEM buffers, one __syncthreads per K-iteration.
#define GBM 128
#define GBN 128
#define GBK 8
__global__ __launch_bounds__(256) void sgemm_bias_kernel(
    const float* __restrict__ A, const float* __restrict__ W,
    const float* __restrict__ bias, float* __restrict__ C,
    int M, int N, int K)
{
    __shared__ float As[2][GBK][GBM];
    __shared__ float Bs[2][GBK][GBN];
    const int tid = threadIdx.x;
    const int bx = blockIdx.x, by = blockIdx.y;
    const int tr = tid >> 4, tc = tid & 15;       // 16x16 thread grid of 8x8 tiles
    const int rowBase = by * GBM, colBase = bx * GBN;

    float acc[8][8];
#pragma unroll
    for (int i = 0; i < 8; i++)
#pragma unroll
        for (int j = 0; j < 8; j++) acc[i][j] = 0.f;

    const int aRow = tid >> 1, aCol = (tid & 1) * 4;
    const int bRow = tid >> 5, bCol = (tid & 31) * 4;
    const float* Aptr = A + (size_t)(rowBase + aRow) * K + aCol;
    const float* Wptr = W + (size_t)bRow * N + colBase + bCol;

    // Preload tile 0 into buffer 0
    {
        float4 av = *(const float4*)(Aptr);
        As[0][aCol + 0][aRow] = av.x;
        As[0][aCol + 1][aRow] = av.y;
        As[0][aCol + 2][aRow] = av.z;
        As[0][aCol + 3][aRow] = av.w;
        *(float4*)&Bs[0][bRow][bCol] = *(const float4*)(Wptr);
    }
    __syncthreads();

    const int NT = K / GBK;
    for (int kt = 0; kt < NT; kt++) {
        const int buf = kt & 1;
        float4 av, wv;
        const bool more = (kt + 1 < NT);
        if (more) {
            av = *(const float4*)(Aptr + (kt + 1) * GBK);
            wv = *(const float4*)(Wptr + (size_t)(kt + 1) * GBK * N);
        }
#pragma unroll
        for (int kk = 0; kk < GBK; kk++) {
            float a[8], b[8];
            *(float4*)(a)     = *(float4*)&As[buf][kk][tr * 8];
            *(float4*)(a + 4) = *(float4*)&As[buf][kk][tr * 8 + 4];
            *(float4*)(b)     = *(float4*)&Bs[buf][kk][tc * 8];
            *(float4*)(b + 4) = *(float4*)&Bs[buf][kk][tc * 8 + 4];
#pragma unroll
            for (int i = 0; i < 8; i++)
#pragma unroll
                for (int j = 0; j < 8; j++)
                    acc[i][j] = fmaf(a[i], b[j], acc[i][j]);
        }
        if (more) {
            const int nb = buf ^ 1;
            As[nb][aCol + 0][aRow] = av.x;
            As[nb][aCol + 1][aRow] = av.y;
            As[nb][aCol + 2][aRow] = av.z;
            As[nb][aCol + 3][aRow] = av.w;
            *(float4*)&Bs[nb][bRow][bCol] = wv;
            __syncthreads();
        }
    }

    const int col = colBase + tc * 8;
    float bv[8];
#pragma unroll
    for (int j = 0; j < 8; j++) bv[j] = bias[col + j];
#pragma unroll
    for (int i = 0; i < 8; i++) {
        int row = rowBase + tr * 8 + i;
        float* cp = C + (size_t)row * N + col;
        float4 r0, r1;
        r0.x = acc[i][0] + bv[0]; r0.y = acc[i][1] + bv[1];
        r0.z = acc[i][2] + bv[2]; r0.w = acc[i][3] + bv[3];
        r1.x = acc[i][4] + bv[4]; r1.y = acc[i][5] + bv[5];
        r1.z = acc[i][6] + bv[6]; r1.w = acc[i][7] + bv[7];
        *(float4*)(cp)     = r0;
        *(float4*)(cp + 4) = r1;
    }
}

// ---------------- Flash attention (fp32, online softmax) -----------------------
#define FB 64
#define QS_STRIDE 132
#define SS_STRIDE 68
#define FLASH_SMEM_FLOATS (3 * FB * QS_STRIDE + FB * SS_STRIDE)

__global__ __launch_bounds__(256) void flash_kernel(
    const float* __restrict__ Qg, const float* __restrict__ Kg,
    const float* __restrict__ Vg, float* __restrict__ Og)
{
    extern __shared__ float sm[];
    float* Qs = sm;                       // [64][132]
    float* Ks = Qs + FB * QS_STRIDE;      // [64][132]
    float* Vs = Ks + FB * QS_STRIDE;      // [64][132]
    float* Ss = Vs + FB * QS_STRIDE;      // [64][68]

    const int tid  = threadIdx.x;
    const int q0   = blockIdx.x * FB;
    const int head = blockIdx.y;
    const int b    = blockIdx.z;
    const size_t base = ((size_t)b * SEQ) * HID + (size_t)head * HD;

    // Load Q tile (64 x 128), coalesced float4
    for (int i = tid; i < FB * (HD / 4); i += 256) {
        int r  = i >> 5;
        int c4 = (i & 31) * 4;
        *(float4*)&Qs[r * QS_STRIDE + c4] =
            *(const float4*)(Qg + base + (size_t)(q0 + r) * HID + c4);
    }

    // row-owner mapping for softmax / PV: 4 threads per row
    const int mr  = tid >> 2;   // 0..63
    const int seg = tid & 3;    // 0..3
    // QK mapping: 4x4 micro-tile
    const int qr = (tid >> 4) * 4;  // 0..60
    const int kc = (tid & 15) * 4;  // 0..60

    float m = -INFINITY, l = 0.f;
    float o[32];
#pragma unroll
    for (int i = 0; i < 32; i++) o[i] = 0.f;
    const float scale = 0.08838834764831845f;  // 1/sqrt(128)

    __syncthreads();

    for (int t0 = 0; t0 < SEQ; t0 += FB) {
        // Load K,V tiles
        for (int i = tid; i < FB * (HD / 4); i += 256) {
            int r  = i >> 5;
            int c4 = (i & 31) * 4;
            size_t g = base + (size_t)(t0 + r) * HID + c4;
            *(float4*)&Ks[r * QS_STRIDE + c4] = *(const float4*)(Kg + g);
            *(float4*)&Vs[r * QS_STRIDE + c4] = *(const float4*)(Vg + g);
        }
        __syncthreads();

        // S = Q K^T * scale : each thread 4x4
        float acc[4][4];
#pragma unroll
        for (int i = 0; i < 4; i++)
#pragma unroll
            for (int j = 0; j < 4; j++) acc[i][j] = 0.f;
#pragma unroll 4
        for (int d = 0; d < HD; d += 4) {
            float4 a[4], bb[4];
#pragma unroll
            for (int i = 0; i < 4; i++) a[i]  = *(float4*)&Qs[(qr + i) * QS_STRIDE + d];
#pragma unroll
            for (int j = 0; j < 4; j++) bb[j] = *(float4*)&Ks[(kc + j) * QS_STRIDE + d];
#pragma unroll
            for (int i = 0; i < 4; i++)
#pragma unroll
                for (int j = 0; j < 4; j++) {
                    acc[i][j] = fmaf(a[i].x, bb[j].x, acc[i][j]);
                    acc[i][j] = fmaf(a[i].y, bb[j].y, acc[i][j]);
                    acc[i][j] = fmaf(a[i].z, bb[j].z, acc[i][j]);
                    acc[i][j] = fmaf(a[i].w, bb[j].w, acc[i][j]);
                }
        }
#pragma unroll
        for (int i = 0; i < 4; i++)
#pragma unroll
            for (int j = 0; j < 4; j++)
                Ss[(qr + i) * SS_STRIDE + kc + j] = acc[i][j] * scale;
        __syncthreads();

        // Online softmax: 4 threads per row, 16 cols each; quad shuffle reduce
        float lmax = -INFINITY;
#pragma unroll
        for (int j = 0; j < 16; j++)
            lmax = fmaxf(lmax, Ss[mr * SS_STRIDE + seg * 16 + j]);
        lmax = fmaxf(lmax, __shfl_xor_sync(0xffffffffu, lmax, 1));
        lmax = fmaxf(lmax, __shfl_xor_sync(0xffffffffu, lmax, 2));
        float mnew = fmaxf(m, lmax);
        float corr = expf(m - mnew);
        float lsum = 0.f;
#pragma unroll
        for (int j = 0; j < 16; j++) {
            float p = expf(Ss[mr * SS_STRIDE + seg * 16 + j] - mnew);
            Ss[mr * SS_STRIDE + seg * 16 + j] = p;
            lsum += p;
        }
        lsum += __shfl_xor_sync(0xffffffffu, lsum, 1);
        lsum += __shfl_xor_sync(0xffffffffu, lsum, 2);
        l = l * corr + lsum;
        m = mnew;
#pragma unroll
        for (int i = 0; i < 32; i++) o[i] *= corr;
        __syncthreads();

        // O += P * V : thread owns row mr, cols [seg*32, seg*32+32)
#pragma unroll 4
        for (int j = 0; j < FB; j++) {
            float p = Ss[mr * SS_STRIDE + j];
            const float* vrow = &Vs[j * QS_STRIDE + seg * 32];
#pragma unroll
            for (int c4 = 0; c4 < 8; c4++) {
                float4 vv = *(const float4*)(vrow + c4 * 4);
                o[c4 * 4 + 0] = fmaf(p, vv.x, o[c4 * 4 + 0]);
                o[c4 * 4 + 1] = fmaf(p, vv.y, o[c4 * 4 + 1]);
                o[c4 * 4 + 2] = fmaf(p, vv.z, o[c4 * 4 + 2]);
                o[c4 * 4 + 3] = fmaf(p, vv.w, o[c4 * 4 + 3]);
            }
        }
        __syncthreads();
    }

    const float inv = 1.f / l;
    float* outp = Og + base + (size_t)(q0 + mr) * HID + seg * 32;
#pragma unroll
    for (int c4 = 0; c4 < 8; c4++) {
        float4 vv;
        vv.x = o[c4 * 4 + 0] * inv;
        vv.y = o[c4 * 4 + 1] * inv;
        vv.z = o[c4 * 4 + 2] * inv;
        vv.w = o[c4 * 4 + 3] * inv;
        *(float4*)(outp + c4 * 4) = vv;
    }
}

// ---------------- launch -------------------------------------------------------
extern "C" void kernel_launch(void* const* d_in, const int* in_sizes, int n_in,
                              void* d_out, int out_size) {
    const float* x  = (const float*)d_in[0];
    const float* Wq = (const float*)d_in[1];
    const float* bq = (const float*)d_in[2];
    const float* Wk = (const float*)d_in[3];
    const float* bk = (const float*)d_in[4];
    const float* Wv = (const float*)d_in[5];
    const float* bv = (const float*)d_in[6];
    const float* Wo = (const float*)d_in[7];
    const float* bo = (const float*)d_in[8];
    float* out = (float*)d_out;

    float *qp, *kp, *vp, *cp;
    cudaGetSymbolAddress((void**)&qp, g_q);
    cudaGetSymbolAddress((void**)&kp, g_k);
    cudaGetSymbolAddress((void**)&vp, g_v);
    cudaGetSymbolAddress((void**)&cp, g_ctx);

    // sin/cos table
    {
        int n = SEQ * (HD / 2);
        sincos_table_kernel<<<(n + 255) / 256, 256>>>();
    }

    dim3 ggrid(HID / GBN, MTOT / GBM);   // (16, 32)
    sgemm_bias_kernel<<<ggrid, 256>>>(x, Wq, bq, qp, MTOT, HID, HID);
    sgemm_bias_kernel<<<ggrid, 256>>>(x, Wk, bk, kp, MTOT, HID, HID);
    sgemm_bias_kernel<<<ggrid, 256>>>(x, Wv, bv, vp, MTOT, HID, HID);

    {
        int n = BATCH * SEQ * HID / 2;
        rope_kernel<<<(n + 255) / 256, 256>>>();
    }

    const int flash_smem = FLASH_SMEM_FLOATS * (int)sizeof(float);
    cudaFuncSetAttribute(flash_kernel,
                         cudaFuncAttributeMaxDynamicSharedMemorySize, flash_smem);
    flash_kernel<<<dim3(SEQ / FB, NH, BATCH), 256, flash_smem>>>(qp, kp, vp, cp);

    sgemm_bias_kernel<<<ggrid, 256>>>(cp, Wo, bo, out, MTOT, HID, HID);
}

// round 5
// speedup vs baseline: 3.0655x; 3.0655x over previous
#include <cuda_runtime.h>
#include <math.h>

// Problem constants
#define BATCH 2
#define SEQ   2048
#define HID   2048
#define NH    16
#define HD    128
#define MTOT  (BATCH*SEQ)   // 4096

// ---------------- scratch (device globals: allocation-free rule) ----------------
__device__ float g_q[BATCH*SEQ*HID];
__device__ float g_k[BATCH*SEQ*HID];
__device__ float g_v[BATCH*SEQ*HID];
__device__ float g_ctx[BATCH*SEQ*HID];
__device__ float g_sin[SEQ*HD];
__device__ float g_cos[SEQ*HD];

// ---------------- RoPE sin/cos table (double precision, tiny kernel) ------------
__global__ void sincos_table_kernel() {
    int idx = blockIdx.x * blockDim.x + threadIdx.x;   // over SEQ * HD/2
    if (idx >= SEQ * (HD / 2)) return;
    int pos = idx / (HD / 2);
    int j   = idx % (HD / 2);
    double inv = exp((-2.0 * (double)j / (double)HD) * log(10000.0));
    double ang = (double)pos * inv;
    float s = (float)sin(ang);
    float c = (float)cos(ang);
    g_sin[pos * HD + 2 * j]     = s;
    g_sin[pos * HD + 2 * j + 1] = s;
    g_cos[pos * HD + 2 * j]     = c;
    g_cos[pos * HD + 2 * j + 1] = c;
}

// ---------------- RoPE apply (q and k in-place) --------------------------------
__global__ void rope_kernel() {
    int idx = blockIdx.x * blockDim.x + threadIdx.x;   // over BATCH*SEQ*HID/2 pairs
    const int total = BATCH * SEQ * HID / 2;
    if (idx >= total) return;
    int pair = idx % (HID / 2);        // pair index within row
    int row  = idx / (HID / 2);
    int s    = row % SEQ;
    int d    = (pair * 2) % HD;        // even position within head
    float sn = g_sin[s * HD + d];
    float cs = g_cos[s * HD + d];
    int base = row * HID + pair * 2;
    float2 q = *(float2*)&g_q[base];
    float2 k = *(float2*)&g_k[base];
    float2 qo, ko;
    qo.x = q.x * cs - q.y * sn;  qo.y = q.y * cs + q.x * sn;
    ko.x = k.x * cs - k.y * sn;  ko.y = k.y * cs + k.x * sn;
    *(float2*)&g_q[base] = qo;
    *(float2*)&g_k[base] = ko;
}

// ---------------- SGEMM with bias: C[M,N] = A[M,K] * W[K,N] + bias -------------
#define GBM 128
#define GBN 128
#define GBK 8
__global__ __launch_bounds__(256) void sgemm_bias_kernel(
    const float* __restrict__ A, const float* __restrict__ W,
    const float* __restrict__ bias, float* __restrict__ C,
    int M, int N, int K)
{
    __shared__ float As[2][GBK][GBM];
    __shared__ float Bs[2][GBK][GBN];
    const int tid = threadIdx.x;
    const int bx = blockIdx.x, by = blockIdx.y;
    const int tr = tid >> 4, tc = tid & 15;
    const int rowBase = by * GBM, colBase = bx * GBN;

    float acc[8][8];
#pragma unroll
    for (int i = 0; i < 8; i++)
#pragma unroll
        for (int j = 0; j < 8; j++) acc[i][j] = 0.f;

    const int aRow = tid >> 1, aCol = (tid & 1) * 4;
    const int bRow = tid >> 5, bCol = (tid & 31) * 4;
    const float* Aptr = A + (size_t)(rowBase + aRow) * K + aCol;
    const float* Wptr = W + (size_t)bRow * N + colBase + bCol;

    {
        float4 av = *(const float4*)(Aptr);
        As[0][aCol + 0][aRow] = av.x;
        As[0][aCol + 1][aRow] = av.y;
        As[0][aCol + 2][aRow] = av.z;
        As[0][aCol + 3][aRow] = av.w;
        *(float4*)&Bs[0][bRow][bCol] = *(const float4*)(Wptr);
    }
    __syncthreads();

    const int NT = K / GBK;
    for (int kt = 0; kt < NT; kt++) {
        const int buf = kt & 1;
        float4 av, wv;
        const bool more = (kt + 1 < NT);
        if (more) {
            av = *(const float4*)(Aptr + (kt + 1) * GBK);
            wv = *(const float4*)(Wptr + (size_t)(kt + 1) * GBK * N);
        }
#pragma unroll
        for (int kk = 0; kk < GBK; kk++) {
            float a[8], b[8];
            *(float4*)(a)     = *(float4*)&As[buf][kk][tr * 8];
            *(float4*)(a + 4) = *(float4*)&As[buf][kk][tr * 8 + 4];
            *(float4*)(b)     = *(float4*)&Bs[buf][kk][tc * 8];
            *(float4*)(b + 4) = *(float4*)&Bs[buf][kk][tc * 8 + 4];
#pragma unroll
            for (int i = 0; i < 8; i++)
#pragma unroll
                for (int j = 0; j < 8; j++)
                    acc[i][j] = fmaf(a[i], b[j], acc[i][j]);
        }
        if (more) {
            const int nb = buf ^ 1;
            As[nb][aCol + 0][aRow] = av.x;
            As[nb][aCol + 1][aRow] = av.y;
            As[nb][aCol + 2][aRow] = av.z;
            As[nb][aCol + 3][aRow] = av.w;
            *(float4*)&Bs[nb][bRow][bCol] = wv;
            __syncthreads();
        }
    }

    const int col = colBase + tc * 8;
    float bv[8];
#pragma unroll
    for (int j = 0; j < 8; j++) bv[j] = bias[col + j];
#pragma unroll
    for (int i = 0; i < 8; i++) {
        int row = rowBase + tr * 8 + i;
        float* cp = C + (size_t)row * N + col;
        float4 r0, r1;
        r0.x = acc[i][0] + bv[0]; r0.y = acc[i][1] + bv[1];
        r0.z = acc[i][2] + bv[2]; r0.w = acc[i][3] + bv[3];
        r1.x = acc[i][4] + bv[4]; r1.y = acc[i][5] + bv[5];
        r1.z = acc[i][6] + bv[6]; r1.w = acc[i][7] + bv[7];
        *(float4*)(cp)     = r0;
        *(float4*)(cp + 4) = r1;
    }
}

// ---------------- TF32 helpers --------------------------------------------------
__device__ __forceinline__ unsigned f2tf32(float f) {
    unsigned r;
    asm("cvt.rna.tf32.f32 %0, %1;" : "=r"(r) : "f"(f));
    return r;
}
__device__ __forceinline__ void mma_tf32(float c[4],
    unsigned a0, unsigned a1, unsigned a2, unsigned a3,
    unsigned b0, unsigned b1)
{
    asm volatile(
        "mma.sync.aligned.m16n8k8.row.col.f32.tf32.tf32.f32 "
        "{%0,%1,%2,%3}, {%4,%5,%6,%7}, {%8,%9}, {%0,%1,%2,%3};"
        : "+f"(c[0]), "+f"(c[1]), "+f"(c[2]), "+f"(c[3])
        : "r"(a0), "r"(a1), "r"(a2), "r"(a3), "r"(b0), "r"(b1));
}

// ---------------- Flash attention (TF32 tensor-core, online softmax) ------------
// CTA: 256 threads = 8 warps. 128 q-rows per CTA; KV tiles of 64 rows.
// Warp w owns q-row band [16w, 16w+16). Softmax stats are warp-private.
#define QROWS 128
#define KTILE 64
#define QSTR  132   // Q/K smem row stride (words)
#define VSTR  136   // V smem row stride
#define PSTR  68    // P smem row stride
#define FLASH_SMEM_WORDS (QROWS*QSTR + KTILE*QSTR + KTILE*VSTR + QROWS*PSTR)

__global__ __launch_bounds__(256, 1) void flash_tf32_kernel(
    const float* __restrict__ Qg, const float* __restrict__ Kg,
    const float* __restrict__ Vg, float* __restrict__ Og)
{
    extern __shared__ unsigned smu[];
    unsigned* Qs = smu;                      // [128][132] tf32 bits (pre-scaled)
    unsigned* Ks = Qs + QROWS * QSTR;        // [64][132]
    unsigned* Vs = Ks + KTILE * QSTR;        // [64][136]
    unsigned* Ps = Vs + KTILE * VSTR;        // [128][68]

    const int tid  = threadIdx.x;
    const int warp = tid >> 5;
    const int lane = tid & 31;
    const int g    = lane >> 2;   // group id 0..7
    const int t    = lane & 3;    // thread-in-group 0..3

    const int q0   = blockIdx.x * QROWS;
    const int head = blockIdx.y;
    const int b    = blockIdx.z;
    const size_t base = ((size_t)b * SEQ) * HID + (size_t)head * HD;

    const float scale = 0.08838834764831845f;  // 1/sqrt(128)

    // Load Q tile (128 x 128), fold scale, convert to tf32
    for (int i = tid; i < QROWS * (HD / 4); i += 256) {
        int r  = i >> 5;
        int c4 = (i & 31) * 4;
        float4 v = *(const float4*)(Qg + base + (size_t)(q0 + r) * HID + c4);
        unsigned* dst = &Qs[r * QSTR + c4];
        dst[0] = f2tf32(v.x * scale);
        dst[1] = f2tf32(v.y * scale);
        dst[2] = f2tf32(v.z * scale);
        dst[3] = f2tf32(v.w * scale);
    }

    float oacc[16][4];
#pragma unroll
    for (int i = 0; i < 16; i++)
#pragma unroll
        for (int j = 0; j < 4; j++) oacc[i][j] = 0.f;
    float m0 = -INFINITY, m1 = -INFINITY, l0 = 0.f, l1 = 0.f;

    const int rowA = 16 * warp + g;       // band-local A rows: rowA, rowA+8

    for (int t0 = 0; t0 < SEQ; t0 += KTILE) {
        __syncthreads();   // previous PV finished reading Vs / QK reading Ks
        // Load K,V tiles (64 x 128), convert to tf32
        for (int i = tid; i < KTILE * (HD / 4); i += 256) {
            int r  = i >> 5;
            int c4 = (i & 31) * 4;
            size_t goff = base + (size_t)(t0 + r) * HID + c4;
            float4 kv = *(const float4*)(Kg + goff);
            float4 vv = *(const float4*)(Vg + goff);
            unsigned* kd = &Ks[r * QSTR + c4];
            kd[0] = f2tf32(kv.x); kd[1] = f2tf32(kv.y);
            kd[2] = f2tf32(kv.z); kd[3] = f2tf32(kv.w);
            unsigned* vd = &Vs[r * VSTR + c4];
            vd[0] = f2tf32(vv.x); vd[1] = f2tf32(vv.y);
            vd[2] = f2tf32(vv.z); vd[3] = f2tf32(vv.w);
        }
        __syncthreads();

        // ---- S = Q K^T (scale pre-folded). Warp: 16 rows x 64 cols ----
        float sacc[8][4];
#pragma unroll
        for (int i = 0; i < 8; i++)
#pragma unroll
            for (int j = 0; j < 4; j++) sacc[i][j] = 0.f;
#pragma unroll
        for (int ks = 0; ks < 16; ks++) {
            const int k0 = ks * 8;
            unsigned a0 = Qs[rowA * QSTR + k0 + t];
            unsigned a1 = Qs[(rowA + 8) * QSTR + k0 + t];
            unsigned a2 = Qs[rowA * QSTR + k0 + t + 4];
            unsigned a3 = Qs[(rowA + 8) * QSTR + k0 + t + 4];
#pragma unroll
            for (int nt = 0; nt < 8; nt++) {
                unsigned b0 = Ks[(8 * nt + g) * QSTR + k0 + t];
                unsigned b1 = Ks[(8 * nt + g) * QSTR + k0 + t + 4];
                mma_tf32(sacc[nt], a0, a1, a2, a3, b0, b1);
            }
        }

        // ---- online softmax (warp-private; rows rowA and rowA+8) ----
        float mx0 = -INFINITY, mx1 = -INFINITY;
#pragma unroll
        for (int nt = 0; nt < 8; nt++) {
            mx0 = fmaxf(mx0, fmaxf(sacc[nt][0], sacc[nt][1]));
            mx1 = fmaxf(mx1, fmaxf(sacc[nt][2], sacc[nt][3]));
        }
        mx0 = fmaxf(mx0, __shfl_xor_sync(0xffffffffu, mx0, 1));
        mx0 = fmaxf(mx0, __shfl_xor_sync(0xffffffffu, mx0, 2));
        mx1 = fmaxf(mx1, __shfl_xor_sync(0xffffffffu, mx1, 1));
        mx1 = fmaxf(mx1, __shfl_xor_sync(0xffffffffu, mx1, 2));
        float mn0 = fmaxf(m0, mx0), mn1 = fmaxf(m1, mx1);
        float corr0 = __expf(m0 - mn0), corr1 = __expf(m1 - mn1);
        float sum0 = 0.f, sum1 = 0.f;
#pragma unroll
        for (int nt = 0; nt < 8; nt++) {
            float p00 = __expf(sacc[nt][0] - mn0);
            float p01 = __expf(sacc[nt][1] - mn0);
            float p10 = __expf(sacc[nt][2] - mn1);
            float p11 = __expf(sacc[nt][3] - mn1);
            sum0 += p00 + p01;
            sum1 += p10 + p11;
            unsigned* pr0 = &Ps[rowA * PSTR + 8 * nt + 2 * t];
            unsigned* pr1 = &Ps[(rowA + 8) * PSTR + 8 * nt + 2 * t];
            pr0[0] = f2tf32(p00); pr0[1] = f2tf32(p01);
            pr1[0] = f2tf32(p10); pr1[1] = f2tf32(p11);
        }
        sum0 += __shfl_xor_sync(0xffffffffu, sum0, 1);
        sum0 += __shfl_xor_sync(0xffffffffu, sum0, 2);
        sum1 += __shfl_xor_sync(0xffffffffu, sum1, 1);
        sum1 += __shfl_xor_sync(0xffffffffu, sum1, 2);
        l0 = l0 * corr0 + sum0;  m0 = mn0;
        l1 = l1 * corr1 + sum1;  m1 = mn1;
#pragma unroll
        for (int nt = 0; nt < 16; nt++) {
            oacc[nt][0] *= corr0; oacc[nt][1] *= corr0;
            oacc[nt][2] *= corr1; oacc[nt][3] *= corr1;
        }
        __syncwarp();

        // ---- O += P V : warp 16 rows x 128 cols, k = 64 ----
#pragma unroll
        for (int ks = 0; ks < 8; ks++) {
            const int k0 = ks * 8;
            unsigned a0 = Ps[rowA * PSTR + k0 + t];
            unsigned a1 = Ps[(rowA + 8) * PSTR + k0 + t];
            unsigned a2 = Ps[rowA * PSTR + k0 + t + 4];
            unsigned a3 = Ps[(rowA + 8) * PSTR + k0 + t + 4];
#pragma unroll
            for (int nt = 0; nt < 16; nt++) {
                unsigned b0 = Vs[(k0 + t) * VSTR + 8 * nt + g];
                unsigned b1 = Vs[(k0 + t + 4) * VSTR + 8 * nt + g];
                mma_tf32(oacc[nt], a0, a1, a2, a3, b0, b1);
            }
        }
    }

    // ---- epilogue: normalize + write ----
    const float inv0 = 1.f / l0, inv1 = 1.f / l1;
    const int grow0 = q0 + 16 * warp + g;
    const int grow1 = grow0 + 8;
#pragma unroll
    for (int nt = 0; nt < 16; nt++) {
        int col = 8 * nt + 2 * t;
        float2 v0 = make_float2(oacc[nt][0] * inv0, oacc[nt][1] * inv0);
        float2 v1 = make_float2(oacc[nt][2] * inv1, oacc[nt][3] * inv1);
        *(float2*)(Og + base + (size_t)grow0 * HID + col) = v0;
        *(float2*)(Og + base + (size_t)grow1 * HID + col) = v1;
    }
}

// ---------------- launch -------------------------------------------------------
extern "C" void kernel_launch(void* const* d_in, const int* in_sizes, int n_in,
                              void* d_out, int out_size) {
    const float* x  = (const float*)d_in[0];
    const float* Wq = (const float*)d_in[1];
    const float* bq = (const float*)d_in[2];
    const float* Wk = (const float*)d_in[3];
    const float* bk = (const float*)d_in[4];
    const float* Wv = (const float*)d_in[5];
    const float* bv = (const float*)d_in[6];
    const float* Wo = (const float*)d_in[7];
    const float* bo = (const float*)d_in[8];
    float* out = (float*)d_out;

    float *qp, *kp, *vp, *cp;
    cudaGetSymbolAddress((void**)&qp, g_q);
    cudaGetSymbolAddress((void**)&kp, g_k);
    cudaGetSymbolAddress((void**)&vp, g_v);
    cudaGetSymbolAddress((void**)&cp, g_ctx);

    {
        int n = SEQ * (HD / 2);
        sincos_table_kernel<<<(n + 255) / 256, 256>>>();
    }

    dim3 ggrid(HID / GBN, MTOT / GBM);   // (16, 32)
    sgemm_bias_kernel<<<ggrid, 256>>>(x, Wq, bq, qp, MTOT, HID, HID);
    sgemm_bias_kernel<<<ggrid, 256>>>(x, Wk, bk, kp, MTOT, HID, HID);
    sgemm_bias_kernel<<<ggrid, 256>>>(x, Wv, bv, vp, MTOT, HID, HID);

    {
        int n = BATCH * SEQ * HID / 2;
        rope_kernel<<<(n + 255) / 256, 256>>>();
    }

    const int flash_smem = FLASH_SMEM_WORDS * (int)sizeof(unsigned);  // ~167 KB
    cudaFuncSetAttribute(flash_tf32_kernel,
                         cudaFuncAttributeMaxDynamicSharedMemorySize, flash_smem);
    flash_tf32_kernel<<<dim3(SEQ / QROWS, NH, BATCH), 256, flash_smem>>>(qp, kp, vp, cp);

    sgemm_bias_kernel<<<ggrid, 256>>>(cp, Wo, bo, out, MTOT, HID, HID);
}